// round 1
// baseline (speedup 1.0000x reference)
#include <cuda_runtime.h>
#include <cstdint>

#define B_ 128
#define I_ 64
#define S_ 2048
#define H_ 128
#define O_ 64
#define CLUSTER 8
#define GROWS 8   // batch rows per cluster
#define NTHR 512

// scratch: x transposed to [t][b][i] for contiguous per-step access
__device__ float g_xT[(size_t)S_ * B_ * I_];

struct Smem {
  float Wout[192][64];      // rows 0..63: Wx_out, 64..191: Wh_out (local 64 gate cols)
  float Win[256][64];       // rows 0..127: Wx_in, 128..255: Wh_in
  float Wlin[8][128];       // this CTA's 8 output rows of W_lin
  float bo[64];
  float bi[64];
  float blin[8];
  float in[192][8];         // [k][row]; k<64: x_t, k>=64: h (cluster-shared h)
  float iin[256][8];        // [k][row]; k<128: x_in, else h_in (cluster-shared)
  float partial[8][64][8];  // [ksplit][col][row]
  float act[64][8];
  float o_g[16][8];
  float c_g[16][8];
  float cn_g[16][8];
};

__device__ __forceinline__ float sigm_f(float x) {
  return __fdividef(1.f, 1.f + __expf(-x));
}
__device__ __forceinline__ float tanh_f(float x) {
  x = fminf(fmaxf(x, -15.f), 15.f);
  float e = __expf(2.f * x);
  return __fdividef(e - 1.f, e + 1.f);
}
__device__ __forceinline__ void ffma2(unsigned long long& d, unsigned long long a,
                                      unsigned long long b) {
  asm("fma.rn.f32x2 %0, %1, %2, %0;" : "+l"(d) : "l"(a), "l"(b));
}
__device__ __forceinline__ unsigned long long dupf(float w) {
  unsigned long long r;
  asm("mov.b64 %0, {%1, %1};" : "=l"(r) : "f"(w));
  return r;
}
__device__ __forceinline__ uint32_t mapa_u32(uint32_t addr, uint32_t r) {
  uint32_t o;
  asm("mapa.shared::cluster.u32 %0, %1, %2;" : "=r"(o) : "r"(addr), "r"(r));
  return o;
}
__device__ __forceinline__ void stc(uint32_t addr, float v) {
  asm volatile("st.shared::cluster.f32 [%0], %1;" ::"r"(addr), "f"(v));
}
__device__ __forceinline__ void cluster_sync_() {
  asm volatile("barrier.cluster.arrive.aligned;" ::: "memory");
  asm volatile("barrier.cluster.wait.aligned;" ::: "memory");
}

// One GEMV slice: warp = (colgroup, ksplit); 8 packed-f32x2 row accumulators.
template <int KB>
__device__ __forceinline__ void gemv(const float* __restrict__ W, const float* __restrict__ in,
                                     float* __restrict__ partial, int warp, int lane) {
  const int cg = warp & 1;
  const int ks = warp >> 1;
  const int col = cg * 32 + lane;
  const int k0 = ks * KB;
  unsigned long long a0 = 0ull, a1 = 0ull, a2 = 0ull, a3 = 0ull;
#pragma unroll
  for (int kk = 0; kk < KB; ++kk) {
    const int k = k0 + kk;
    unsigned long long wp = dupf(W[k * 64 + col]);           // LDS.32, conflict-free
    ulonglong2 u0 = *reinterpret_cast<const ulonglong2*>(in + k * 8);      // rows 0..3 (bcast)
    ulonglong2 u1 = *reinterpret_cast<const ulonglong2*>(in + k * 8 + 4);  // rows 4..7
    ffma2(a0, wp, u0.x);
    ffma2(a1, wp, u0.y);
    ffma2(a2, wp, u1.x);
    ffma2(a3, wp, u1.y);
  }
  ulonglong2* p = reinterpret_cast<ulonglong2*>(partial + (ks * 64 + col) * 8);
  p[0] = make_ulonglong2(a0, a1);
  p[1] = make_ulonglong2(a2, a3);
}

__global__ void transpose_x(const float* __restrict__ x) {
  __shared__ float tile[32][33];
  int b = blockIdx.z;
  int i0 = blockIdx.y * 32;
  int t0 = blockIdx.x * 32;
  int tx = threadIdx.x, ty = threadIdx.y;
#pragma unroll
  for (int j = 0; j < 32; j += 8)
    tile[ty + j][tx] = x[(size_t)b * (I_ * S_) + (size_t)(i0 + ty + j) * S_ + t0 + tx];
  __syncthreads();
#pragma unroll
  for (int j = 0; j < 32; j += 8)
    g_xT[(size_t)(t0 + ty + j) * (B_ * I_) + b * I_ + i0 + tx] = tile[tx][ty + j];
}

__global__ void __launch_bounds__(NTHR, 1) __cluster_dims__(CLUSTER, 1, 1)
nlstm_kernel(const float* __restrict__ Wx_out, const float* __restrict__ Wh_out,
             const float* __restrict__ b_out, const float* __restrict__ Wx_in,
             const float* __restrict__ Wh_in, const float* __restrict__ b_in,
             const float* __restrict__ W_lin, const float* __restrict__ b_lin,
             float* __restrict__ out) {
  extern __shared__ __align__(16) char smem_raw[];
  Smem& sm = *reinterpret_cast<Smem*>(smem_raw);
  const int tid = threadIdx.x;
  const int warp = tid >> 5, lane = tid & 31;
  const int rank = blockIdx.x & (CLUSTER - 1);
  const int b0 = (blockIdx.x >> 3) * GROWS;

  // ---- load weight slices: local col c -> global gate col ----
  for (int idx = tid; idx < 192 * 64; idx += NTHR) {
    int k = idx >> 6, c = idx & 63;
    int gcol = ((c >> 4) << 7) + (rank << 4) + (c & 15);
    sm.Wout[k][c] = (k < 64) ? Wx_out[k * 512 + gcol] : Wh_out[(k - 64) * 512 + gcol];
  }
  for (int idx = tid; idx < 256 * 64; idx += NTHR) {
    int k = idx >> 6, c = idx & 63;
    int gcol = ((c >> 4) << 7) + (rank << 4) + (c & 15);
    sm.Win[k][c] = (k < 128) ? Wx_in[k * 512 + gcol] : Wh_in[(k - 128) * 512 + gcol];
  }
  for (int idx = tid; idx < 8 * 128; idx += NTHR)
    sm.Wlin[idx >> 7][idx & 127] = W_lin[(rank * 8 + (idx >> 7)) * 128 + (idx & 127)];
  if (tid < 64) {
    int gcol = ((tid >> 4) << 7) + (rank << 4) + (tid & 15);
    sm.bo[tid] = b_out[gcol];
    sm.bi[tid] = b_in[gcol];
  }
  if (tid < 8) sm.blin[tid] = b_lin[rank * 8 + tid];
  for (int idx = tid; idx < 128 * 8; idx += NTHR)
    sm.in[64 + (idx >> 3)][idx & 7] = 0.f;  // h0 = 0
  if (tid < 128) {
    sm.c_g[tid >> 3][tid & 7] = 0.f;
    sm.cn_g[tid >> 3][tid & 7] = 0.f;
  }
  __syncthreads();

  const uint32_t iinx_base = (uint32_t)__cvta_generic_to_shared(&sm.iin[rank * 16][0]);
  const uint32_t iinh_base = (uint32_t)__cvta_generic_to_shared(&sm.iin[128 + rank * 16][0]);
  const uint32_t h_base = (uint32_t)__cvta_generic_to_shared(&sm.in[64 + rank * 16][0]);

  for (int t = 0; t < S_; ++t) {
    // stage x_t into in[0..64)
    {
      int k = tid & 63, row = tid >> 6;
      sm.in[k][row] = g_xT[(size_t)t * (B_ * I_) + (b0 + row) * I_ + k];
    }
    __syncthreads();

    // ---- outer gates: K = 192 ----
    gemv<24>(&sm.Wout[0][0], &sm.in[0][0], &sm.partial[0][0][0], warp, lane);
    __syncthreads();
    {
      int col = tid >> 3, row = tid & 7;
      float s = sm.bo[col];
#pragma unroll
      for (int ks = 0; ks < 8; ++ks) s += sm.partial[ks][col][row];
      sm.act[col][row] = (col >= 48) ? tanh_f(s) : sigm_f(s);
    }
    __syncthreads();
    if (tid < 128) {  // combine: x_in = sig(i)*tanh(g), h_in = sig(f)*c; broadcast
      int jj = tid >> 3, row = tid & 7;
      float iv = sm.act[jj][row];
      float fv = sm.act[16 + jj][row];
      float ov = sm.act[32 + jj][row];
      float gv = sm.act[48 + jj][row];
      float xin = iv * gv;
      float hin = fv * sm.c_g[jj][row];
      sm.o_g[jj][row] = ov;
      uint32_t off = (uint32_t)(jj * 8 + row) * 4;
#pragma unroll
      for (int r = 0; r < CLUSTER; ++r) {
        stc(mapa_u32(iinx_base + off, r), xin);
        stc(mapa_u32(iinh_base + off, r), hin);
      }
    }
    cluster_sync_();

    // ---- inner gates: K = 256 ----
    gemv<32>(&sm.Win[0][0], &sm.iin[0][0], &sm.partial[0][0][0], warp, lane);
    __syncthreads();
    {
      int col = tid >> 3, row = tid & 7;
      float s = sm.bi[col];
#pragma unroll
      for (int ks = 0; ks < 8; ++ks) s += sm.partial[ks][col][row];
      sm.act[col][row] = (col >= 48) ? tanh_f(s) : sigm_f(s);
    }
    __syncthreads();
    if (tid < 128) {  // state update + h broadcast
      int jj = tid >> 3, row = tid & 7;
      float siv = sm.act[jj][row];
      float sfv = sm.act[16 + jj][row];
      float sov = sm.act[32 + jj][row];
      float sgv = sm.act[48 + jj][row];
      float cn = sfv * sm.cn_g[jj][row] + siv * sgv;
      sm.cn_g[jj][row] = cn;
      float c = sov * tanh_f(cn);
      sm.c_g[jj][row] = c;
      float h = sm.o_g[jj][row] * tanh_f(c);
      uint32_t off = (uint32_t)(jj * 8 + row) * 4;
#pragma unroll
      for (int r = 0; r < CLUSTER; ++r) stc(mapa_u32(h_base + off, r), h);
    }
    cluster_sync_();

    // ---- fused output projection: this CTA writes o in [8*rank, 8*rank+8) ----
    if (tid < 64) {
      int row = tid >> 3, oo = tid & 7;
      float a0 = 0.f, a1 = 0.f, a2 = 0.f, a3 = 0.f;
#pragma unroll
      for (int k = 0; k < 128; k += 4) {
        float4 w = *reinterpret_cast<const float4*>(&sm.Wlin[oo][k]);
        a0 += w.x * sm.in[64 + k][row];
        a1 += w.y * sm.in[64 + k + 1][row];
        a2 += w.z * sm.in[64 + k + 2][row];
        a3 += w.w * sm.in[64 + k + 3][row];
      }
      out[((size_t)(b0 + row) * S_ + t) * O_ + rank * 8 + oo] =
          a0 + a1 + a2 + a3 + sm.blin[oo];
    }
  }
}

extern "C" void kernel_launch(void* const* d_in, const int* in_sizes, int n_in,
                              void* d_out, int out_size) {
  (void)in_sizes;
  (void)n_in;
  (void)out_size;
  cudaFuncSetAttribute(nlstm_kernel, cudaFuncAttributeMaxDynamicSharedMemorySize,
                       (int)sizeof(Smem));
  transpose_x<<<dim3(S_ / 32, I_ / 32, B_), dim3(32, 8)>>>((const float*)d_in[0]);
  nlstm_kernel<<<(B_ / GROWS) * CLUSTER, NTHR, sizeof(Smem)>>>(
      (const float*)d_in[1], (const float*)d_in[2], (const float*)d_in[3],
      (const float*)d_in[4], (const float*)d_in[5], (const float*)d_in[6],
      (const float*)d_in[7], (const float*)d_in[8], (float*)d_out);
}

// round 2
// speedup vs baseline: 1.5910x; 1.5910x over previous
#include <cuda_runtime.h>
#include <cstdint>

#define B_ 128
#define I_ 64
#define S_ 2048
#define H_ 128
#define O_ 64
#define CLUSTER 8
#define NTHR 512
#define KS 16
#define KBO 12  // 192 / 16 warps
#define KBI 16  // 256 / 16 warps

// scratch: x transposed to [t][b][i]
__device__ float g_xT[(size_t)S_ * B_ * I_];

struct Smem {
  float in[192][8];           // k<64: x_t ; 64..192: h (cluster-shared)
  float iin[256][8];          // k<128: x_in ; else h_in (cluster-shared)
  float partial[KS][64][8];   // gemv k-split partials
  float Wlin[8][129];         // padded to kill bank conflicts
  float partialP[8][8][9];    // projection k-split partials [kq][oo][row]
  float bo[64], bi[64], blin[8];
  unsigned long long mbar_iin;
  unsigned long long mbar_h;
};

__device__ __forceinline__ float tanh_ap(float x) {
  float y;
  asm("tanh.approx.f32 %0, %1;" : "=f"(y) : "f"(x));
  return y;
}
__device__ __forceinline__ float sigm_t(float x) {
  return fmaf(0.5f, tanh_ap(0.5f * x), 0.5f);
}
__device__ __forceinline__ void ffma2(unsigned long long& d, unsigned long long a,
                                      unsigned long long b) {
  asm("fma.rn.f32x2 %0, %1, %2, %0;" : "+l"(d) : "l"(a), "l"(b));
}
__device__ __forceinline__ unsigned long long dupf(float w) {
  unsigned long long r;
  asm("mov.b64 %0, {%1, %1};" : "=l"(r) : "f"(w));
  return r;
}
__device__ __forceinline__ uint32_t mapa_u32(uint32_t addr, uint32_t r) {
  uint32_t o;
  asm("mapa.shared::cluster.u32 %0, %1, %2;" : "=r"(o) : "r"(addr), "r"(r));
  return o;
}
__device__ __forceinline__ void stc(uint32_t addr, float v) {
  asm volatile("st.shared::cluster.f32 [%0], %1;" ::"r"(addr), "f"(v));
}
__device__ __forceinline__ void fence_cluster() {
  asm volatile("fence.acq_rel.cluster;" ::: "memory");
}
__device__ __forceinline__ void arrive_remote(uint32_t local_mbar, uint32_t r) {
  uint32_t rem = mapa_u32(local_mbar, r);
  asm volatile("mbarrier.arrive.shared::cluster.b64 _, [%0];" ::"r"(rem) : "memory");
}
__device__ __forceinline__ void mbar_init(uint32_t mbar, uint32_t count) {
  asm volatile("mbarrier.init.shared.b64 [%0], %1;" ::"r"(mbar), "r"(count) : "memory");
}
__device__ __forceinline__ void wait_parity_cluster(uint32_t mbar, uint32_t parity) {
  asm volatile(
      "{\n\t.reg .pred P1;\n\t"
      "WL_%=:\n\t"
      "mbarrier.try_wait.parity.acquire.cluster.shared::cta.b64 P1, [%0], %1, 0x989680;\n\t"
      "@P1 bra.uni WD_%=;\n\t"
      "bra.uni WL_%=;\n\t"
      "WD_%=:\n\t}"
      ::"r"(mbar), "r"(parity)
      : "memory");
}
__device__ __forceinline__ void cluster_sync_() {
  asm volatile("barrier.cluster.arrive.aligned;" ::: "memory");
  asm volatile("barrier.cluster.wait.aligned;" ::: "memory");
}

// warp 'ks' covers both 32-col groups with register-resident weights.
template <int KB>
__device__ __forceinline__ void gemv2(const float (&wreg)[2][KB], const float* __restrict__ in_,
                                      float* __restrict__ partial_, int ks, int lane) {
  unsigned long long a00 = 0, a01 = 0, a02 = 0, a03 = 0;
  unsigned long long a10 = 0, a11 = 0, a12 = 0, a13 = 0;
  const float* up = in_ + ks * KB * 8;
#pragma unroll
  for (int kk = 0; kk < KB; ++kk) {
    ulonglong2 u01 = *reinterpret_cast<const ulonglong2*>(up + kk * 8);      // rows 0..3
    ulonglong2 u23 = *reinterpret_cast<const ulonglong2*>(up + kk * 8 + 4);  // rows 4..7
    unsigned long long w0 = dupf(wreg[0][kk]);
    ffma2(a00, w0, u01.x);
    ffma2(a01, w0, u01.y);
    ffma2(a02, w0, u23.x);
    ffma2(a03, w0, u23.y);
    unsigned long long w1 = dupf(wreg[1][kk]);
    ffma2(a10, w1, u01.x);
    ffma2(a11, w1, u01.y);
    ffma2(a12, w1, u23.x);
    ffma2(a13, w1, u23.y);
  }
  {
    ulonglong2* p = reinterpret_cast<ulonglong2*>(partial_ + (ks * 64 + lane) * 8);
    p[0] = make_ulonglong2(a00, a01);
    p[1] = make_ulonglong2(a02, a03);
  }
  {
    ulonglong2* p = reinterpret_cast<ulonglong2*>(partial_ + (ks * 64 + 32 + lane) * 8);
    p[0] = make_ulonglong2(a10, a11);
    p[1] = make_ulonglong2(a12, a13);
  }
}

__global__ void transpose_x(const float* __restrict__ x) {
  __shared__ float tile[32][33];
  int b = blockIdx.z;
  int i0 = blockIdx.y * 32;
  int t0 = blockIdx.x * 32;
  int tx = threadIdx.x, ty = threadIdx.y;
#pragma unroll
  for (int j = 0; j < 32; j += 8)
    tile[ty + j][tx] = x[(size_t)b * (I_ * S_) + (size_t)(i0 + ty + j) * S_ + t0 + tx];
  __syncthreads();
#pragma unroll
  for (int j = 0; j < 32; j += 8)
    g_xT[(size_t)(t0 + ty + j) * (B_ * I_) + b * I_ + i0 + tx] = tile[tx][ty + j];
}

__device__ __forceinline__ void proj_partial(Smem& sm, int tid) {
  // 512 threads: (kq, oo, row); reads h at in[64..192)
  int kq = tid >> 6, oo = (tid >> 3) & 7, row = tid & 7;
  int k0 = kq * 16;
  float pa0 = 0.f, pa1 = 0.f;
#pragma unroll
  for (int kk = 0; kk < 16; kk += 2) {
    pa0 += sm.Wlin[oo][k0 + kk] * sm.in[64 + k0 + kk][row];
    pa1 += sm.Wlin[oo][k0 + kk + 1] * sm.in[64 + k0 + kk + 1][row];
  }
  sm.partialP[kq][oo][row] = pa0 + pa1;
}

__device__ __forceinline__ void proj_reduce_stg(Smem& sm, int ltid, int tout, int rank, int b0,
                                                float* __restrict__ out) {
  int row = ltid & 7, oo = ltid >> 3;
  float s = sm.blin[oo];
#pragma unroll
  for (int kq = 0; kq < 8; ++kq) s += sm.partialP[kq][oo][row];
  out[((size_t)(b0 + row) * S_ + tout) * O_ + rank * 8 + oo] = s;
}

__global__ void __launch_bounds__(NTHR, 1) __cluster_dims__(CLUSTER, 1, 1)
nlstm_kernel(const float* __restrict__ Wx_out, const float* __restrict__ Wh_out,
             const float* __restrict__ b_out, const float* __restrict__ Wx_in,
             const float* __restrict__ Wh_in, const float* __restrict__ b_in,
             const float* __restrict__ W_lin, const float* __restrict__ b_lin,
             float* __restrict__ out) {
  extern __shared__ __align__(16) char smem_raw[];
  Smem& sm = *reinterpret_cast<Smem*>(smem_raw);
  const int tid = threadIdx.x;
  const int warp = tid >> 5, lane = tid & 31;
  const int rank = blockIdx.x & (CLUSTER - 1);
  const int b0 = (blockIdx.x >> 3) * 8;

  // ---- init smem: biases, Wlin, h0 = 0, x(0) stage ----
  if (tid < 64) {
    int gcol = ((tid >> 4) << 7) + (rank << 4) + (tid & 15);
    sm.bo[tid] = b_out[gcol];
    sm.bi[tid] = b_in[gcol];
  }
  if (tid < 8) sm.blin[tid] = b_lin[rank * 8 + tid];
  for (int idx = tid; idx < 8 * 128; idx += NTHR)
    sm.Wlin[idx >> 7][idx & 127] = W_lin[(rank * 8 + (idx >> 7)) * 128 + (idx & 127)];
  for (int idx = tid; idx < 128 * 8; idx += NTHR) sm.in[64 + (idx >> 3)][idx & 7] = 0.f;
  {  // stage x(0)
    int k = tid & 63, row = tid >> 6;
    sm.in[k][row] = g_xT[(size_t)(b0 + row) * I_ + k];
  }
  const uint32_t mb_iin = (uint32_t)__cvta_generic_to_shared(&sm.mbar_iin);
  const uint32_t mb_h = (uint32_t)__cvta_generic_to_shared(&sm.mbar_h);
  if (tid == 0) {
    mbar_init(mb_iin, CLUSTER);
    mbar_init(mb_h, CLUSTER);
  }
  __syncthreads();
  cluster_sync_();

  // ---- register-resident weights ----
  float wO[2][KBO], wI[2][KBI];
#pragma unroll
  for (int cg = 0; cg < 2; ++cg) {
    int c = cg * 32 + lane;
    int gcol = ((c >> 4) << 7) + (rank << 4) + (c & 15);
#pragma unroll
    for (int kk = 0; kk < KBO; ++kk) {
      int k = warp * KBO + kk;
      wO[cg][kk] = (k < 64) ? Wx_out[k * 512 + gcol] : Wh_out[(k - 64) * 512 + gcol];
    }
#pragma unroll
    for (int kk = 0; kk < KBI; ++kk) {
      int k = warp * KBI + kk;
      wI[cg][kk] = (k < 128) ? Wx_in[k * 512 + gcol] : Wh_in[(k - 128) * 512 + gcol];
    }
  }

  const uint32_t iinx_base =
      (uint32_t)__cvta_generic_to_shared(&sm.iin[rank * 16][0]);  // +4096B -> h_in half
  const uint32_t h_base = (uint32_t)__cvta_generic_to_shared(&sm.in[64 + rank * 16][0]);

  float c_reg = 0.f, cn_reg = 0.f, o_save = 0.f;
  float2 xpf = make_float2(0.f, 0.f);

  for (int t = 0; t < S_; ++t) {
    // ---- P1: outer gemv + projection partial for h(t-1) ----
    gemv2<KBO>(wO, &sm.in[0][0], &sm.partial[0][0][0], warp, lane);
    if (t > 0) proj_partial(sm, tid);
    __syncthreads();  // A

    // ---- P2: gate reduce/act/combine + sends | proj reduce+STG | x prefetch ----
    if (tid < 128) {
      int jj = tid >> 3, row = tid & 7;
      float s0 = sm.bo[jj], s1 = sm.bo[16 + jj], s2 = sm.bo[32 + jj], s3 = sm.bo[48 + jj];
#pragma unroll
      for (int ks = 0; ks < KS; ++ks) {
        s0 += sm.partial[ks][jj][row];
        s1 += sm.partial[ks][16 + jj][row];
        s2 += sm.partial[ks][32 + jj][row];
        s3 += sm.partial[ks][48 + jj][row];
      }
      float iv = sigm_t(s0), fv = sigm_t(s1);
      o_save = sigm_t(s2);
      float gv = tanh_ap(s3);
      float xin = iv * gv;
      float hin = fv * c_reg;
      uint32_t off = (uint32_t)tid * 4;
#pragma unroll
      for (int r = 0; r < CLUSTER; ++r) {
        uint32_t a = mapa_u32(iinx_base + off, r);
        stc(a, xin);
        stc(a + 4096, hin);
      }
    } else if (tid < 192) {
      if (t > 0) proj_reduce_stg(sm, tid - 128, t - 1, rank, b0, out);
    } else if (tid >= 256) {
      if (t + 1 < S_) {
        int idx = (tid - 256) * 2;
        xpf = *reinterpret_cast<const float2*>(
            &g_xT[(size_t)(t + 1) * (B_ * I_) + b0 * I_ + idx]);
      }
    }
    __syncthreads();  // B
    if (tid == 0) {
      fence_cluster();
#pragma unroll
      for (int r = 0; r < CLUSTER; ++r) arrive_remote(mb_iin, r);
    }
    wait_parity_cluster(mb_iin, t & 1);

    // ---- P3: inner gemv ----
    gemv2<KBI>(wI, &sm.iin[0][0], &sm.partial[0][0][0], warp, lane);
    __syncthreads();  // C

    // ---- P4: inner reduce/act/state update + h sends | x(t+1) stage ----
    if (tid < 128) {
      int jj = tid >> 3, row = tid & 7;
      float s0 = sm.bi[jj], s1 = sm.bi[16 + jj], s2 = sm.bi[32 + jj], s3 = sm.bi[48 + jj];
#pragma unroll
      for (int ks = 0; ks < KS; ++ks) {
        s0 += sm.partial[ks][jj][row];
        s1 += sm.partial[ks][16 + jj][row];
        s2 += sm.partial[ks][32 + jj][row];
        s3 += sm.partial[ks][48 + jj][row];
      }
      float ii = sigm_t(s0), ff = sigm_t(s1), o2 = sigm_t(s2), gg = tanh_ap(s3);
      cn_reg = ff * cn_reg + ii * gg;
      c_reg = o2 * tanh_ap(cn_reg);
      float h = o_save * tanh_ap(c_reg);
      uint32_t off = (uint32_t)tid * 4;
#pragma unroll
      for (int r = 0; r < CLUSTER; ++r) stc(mapa_u32(h_base + off, r), h);
    } else if (tid >= 256) {
      if (t + 1 < S_) {
        int idx = (tid - 256) * 2;
        int row = idx >> 6, i = idx & 63;
        sm.in[i][row] = xpf.x;
        sm.in[i + 1][row] = xpf.y;
      }
    }
    __syncthreads();  // D
    if (tid == 0) {
      fence_cluster();
#pragma unroll
      for (int r = 0; r < CLUSTER; ++r) arrive_remote(mb_h, r);
    }
    wait_parity_cluster(mb_h, t & 1);
  }

  // ---- epilogue: projection for t = S_-1 ----
  proj_partial(sm, tid);
  __syncthreads();
  if (tid >= 128 && tid < 192) proj_reduce_stg(sm, tid - 128, S_ - 1, rank, b0, out);
}

extern "C" void kernel_launch(void* const* d_in, const int* in_sizes, int n_in,
                              void* d_out, int out_size) {
  (void)in_sizes;
  (void)n_in;
  (void)out_size;
  cudaFuncSetAttribute(nlstm_kernel, cudaFuncAttributeMaxDynamicSharedMemorySize,
                       (int)sizeof(Smem));
  transpose_x<<<dim3(S_ / 32, I_ / 32, B_), dim3(32, 8)>>>((const float*)d_in[0]);
  nlstm_kernel<<<(B_ / 8) * CLUSTER, NTHR, sizeof(Smem)>>>(
      (const float*)d_in[1], (const float*)d_in[2], (const float*)d_in[3],
      (const float*)d_in[4], (const float*)d_in[5], (const float*)d_in[6],
      (const float*)d_in[7], (const float*)d_in[8], (float*)d_out);
}